// round 16
// baseline (speedup 1.0000x reference)
#include <cuda_runtime.h>
#include <cstdint>

#define COLS      32768
#define K_TOP     64
#define NTHREADS  256        // 8 CTAs/SM: finer tail granularity, more de-phased streams
#define CAP       4096
#define EQCAP     256
#define PIVOT     2.0f       // well below the expected 64th-largest (~2.88σ); slow path covers the rest

__device__ __forceinline__ unsigned sortable_bits(float f) {
    unsigned u = __float_as_uint(f);
    return (u & 0x80000000u) ? ~u : (u | 0x80000000u);
}
__device__ __forceinline__ float unsortable_bits(unsigned s) {
    unsigned u = (s & 0x80000000u) ? (s & 0x7fffffffu) : ~s;
    return __uint_as_float(u);
}

// 256-bit streaming load/store (sm_100+). 32B alignment guaranteed by indexing.
__device__ __forceinline__ void ldg256_cs(const float* p, float* v) {
    asm volatile("ld.global.cs.v8.f32 {%0,%1,%2,%3,%4,%5,%6,%7}, [%8];"
                 : "=f"(v[0]), "=f"(v[1]), "=f"(v[2]), "=f"(v[3]),
                   "=f"(v[4]), "=f"(v[5]), "=f"(v[6]), "=f"(v[7])
                 : "l"(p));
}
__device__ __forceinline__ void stg256_zero_cs(float* p) {
    asm volatile("st.global.cs.v8.f32 [%0], {%1,%2,%3,%4,%5,%6,%7,%8};"
                 :: "l"(p),
                    "f"(0.f), "f"(0.f), "f"(0.f), "f"(0.f),
                    "f"(0.f), "f"(0.f), "f"(0.f), "f"(0.f)
                 : "memory");
}

__global__ __launch_bounds__(NTHREADS, 8)
void topk_scatter_kernel(const float* __restrict__ x, float* __restrict__ out) {
    __shared__ unsigned       cand_bits[CAP];
    __shared__ unsigned short cand_idx[CAP];
    __shared__ unsigned short eq_idx[EQCAP];
    __shared__ int            hist[256];
    __shared__ int            ncand_s;
    __shared__ unsigned       cur_s;
    __shared__ int            k_s;
    __shared__ int            cnt_s;
    __shared__ int            eq_cnt;

    const int row = blockIdx.x;
    const int tid = threadIdx.x;
    const int lane = tid & 31;

    const float* __restrict__ xrow = x + (size_t)row * COLS;
    float* __restrict__       orow = out + (size_t)row * COLS;

    if (tid == 0) { ncand_s = 0; eq_cnt = 0; }
    __syncthreads();

    // ---------------- Phase A: fused pass — 256-bit stream-read + 256-bit zero-write,
    // ---------------- interleaved ld/st; candidate check per 32B chunk; rare smem compaction.
    // Row = 4096 float8-chunks; 256 threads -> 16 chunks/thread; 2 chunks (64B) in flight/step.
    {
        const float* xp = xrow + (size_t)tid * 8;
        float*       op = orow + (size_t)tid * 8;
        constexpr size_t STRIDE = (size_t)NTHREADS * 8;          // elements per chunk-wave
        int jbase = tid * 8;                                     // element index of chunk 0

        constexpr int CHUNKS = COLS / 8 / NTHREADS;              // 16
        #pragma unroll
        for (int i = 0; i < CHUNKS; i += 2) {
            float a[8], b[8];
            ldg256_cs(xp, a);
            stg256_zero_cs(op);
            ldg256_cs(xp + STRIDE, b);
            stg256_zero_cs(op + STRIDE);

            // one 8-wide check per 32B chunk (taken ~16.8%)
            #pragma unroll
            for (int h = 0; h < 2; ++h) {
                const float* w = h ? b : a;
                const int j8 = jbase + (h ? (int)STRIDE : 0);
                float m01 = fmaxf(w[0], w[1]), m23 = fmaxf(w[2], w[3]);
                float m45 = fmaxf(w[4], w[5]), m67 = fmaxf(w[6], w[7]);
                if (fmaxf(fmaxf(m01, m23), fmaxf(m45, m67)) >= PIVOT) {
                    #pragma unroll
                    for (int c = 0; c < 8; ++c) {
                        const float val = w[c];
                        if (val >= PIVOT) {
                            int pos = atomicAdd(&ncand_s, 1);
                            if (pos < CAP) {
                                cand_bits[pos] = __float_as_uint(val);  // positive -> bit order = value order
                                cand_idx[pos]  = (unsigned short)(j8 + c);
                            }
                        }
                    }
                }
            }
            xp += 2 * STRIDE;
            op += 2 * STRIDE;
            jbase += 2 * (int)STRIDE;
        }
    }
    __syncthreads();
    const int ncand = ncand_s;

    if (ncand >= K_TOP && ncand <= CAP) {
        // ---------------- Phase B: 4x8-bit radix select, K-th largest among candidates ----------------
        if (tid == 0) { cur_s = 0u; k_s = K_TOP; }
        #pragma unroll
        for (int pass = 0; pass < 4; ++pass) {
            const int shift = 24 - 8 * pass;
            hist[tid] = 0;                        // NTHREADS == 256
            __syncthreads();

            const unsigned cur = cur_s;
            const int k = k_s;
            for (int j = tid; j < ncand; j += NTHREADS) {
                unsigned u = cand_bits[j];
                bool match = (pass == 0) || ((u >> (shift + 8)) == cur);
                if (match) atomicAdd(&hist[(u >> shift) & 255u], 1);
            }
            __syncthreads();

            if (tid < 32) {
                // lane l owns digits [255-8l .. 248-8l], top-down
                int h[8]; int s = 0;
                #pragma unroll
                for (int q = 0; q < 8; ++q) { h[q] = hist[255 - 8 * lane - q]; s += h[q]; }
                int pre = s;
                #pragma unroll
                for (int d = 1; d < 32; d <<= 1) {
                    int t2 = __shfl_up_sync(0xffffffffu, pre, d);
                    if (lane >= d) pre += t2;
                }
                pre -= s;  // exclusive prefix (count of strictly larger digits)
                bool hit = (pre < k) && (pre + s >= k);
                unsigned hm = __ballot_sync(0xffffffffu, hit);
                int hl = __ffs(hm) - 1;
                if (lane == hl) {
                    int acc = pre;
                    #pragma unroll
                    for (int q = 0; q < 8; ++q) {
                        int d = 255 - 8 * lane - q;
                        if (acc + h[q] >= k) { cur_s = (cur << 8) | (unsigned)d; k_s = k - acc; break; }
                        acc += h[q];
                    }
                }
            }
            __syncthreads();
        }
        const unsigned thr_bits = cur_s;              // exact K-th largest (positive float bits)
        const int      need_eq  = k_s;                // # of tied-at-threshold elements to KEEP
        const float    thr_f    = __uint_as_float(thr_bits);

        // ---------------- Phase C: scatter strictly-greater winners; collect boundary ties ----------------
        for (int j = tid; j < ncand; j += NTHREADS) {
            unsigned u = cand_bits[j];
            if (u > thr_bits) {
                orow[cand_idx[j]] = fmaxf(__uint_as_float(u), 0.f);
            } else if (u == thr_bits) {
                int p = atomicAdd(&eq_cnt, 1);
                if (p < EQCAP) eq_idx[p] = cand_idx[j];
            }
        }
        __syncthreads();

        // Tie-break like XLA top_k: among equal values, lowest indices win.
        const int ce = (eq_cnt < EQCAP) ? eq_cnt : EQCAP;
        const float thr_relu = fmaxf(thr_f, 0.f);
        for (int j = tid; j < ce; j += NTHREADS) {
            const unsigned short me = eq_idx[j];
            int r = 0;
            for (int i = 0; i < ce; ++i) r += (eq_idx[i] < me) ? 1 : 0;
            if (r < need_eq) orow[me] = thr_relu;
        }
    } else {
        // ---------------- Slow path (general, exact; never triggers for this input) ----------------
        // Output row already zeroed by Phase A.

        // 32-step bit-descend: largest thr with count(bits >= thr) >= K  ==  bits of K-th largest
        unsigned thr = 0u;
        for (int b = 31; b >= 0; --b) {
            const unsigned T = thr | (1u << b);
            if (tid == 0) cnt_s = 0;
            __syncthreads();
            int c = 0;
            for (int j = tid; j < COLS; j += NTHREADS)
                c += (sortable_bits(xrow[j]) >= T) ? 1 : 0;
            #pragma unroll
            for (int d = 16; d; d >>= 1) c += __shfl_down_sync(0xffffffffu, c, d);
            if (lane == 0) atomicAdd(&cnt_s, c);
            __syncthreads();
            if (cnt_s >= K_TOP) thr = T;
            __syncthreads();               // protect cnt_s read vs next-iter reset
        }

        // count strictly greater -> need_eq
        if (tid == 0) cnt_s = 0;
        __syncthreads();
        {
            int c = 0;
            for (int j = tid; j < COLS; j += NTHREADS)
                c += (sortable_bits(xrow[j]) > thr) ? 1 : 0;
            #pragma unroll
            for (int d = 16; d; d >>= 1) c += __shfl_down_sync(0xffffffffu, c, d);
            if (lane == 0) atomicAdd(&cnt_s, c);
        }
        __syncthreads();
        const int need_eq = K_TOP - cnt_s;
        __syncthreads();

        // scatter strictly-greater; collect ties
        for (int j = tid; j < COLS; j += NTHREADS) {
            float v = xrow[j];
            unsigned s = sortable_bits(v);
            if (s > thr) {
                orow[j] = fmaxf(v, 0.f);
            } else if (s == thr) {
                int p = atomicAdd(&eq_cnt, 1);
                if (p < EQCAP) eq_idx[p] = (unsigned short)j;
            }
        }
        __syncthreads();
        const int ce = (eq_cnt < EQCAP) ? eq_cnt : EQCAP;
        const float thr_relu = fmaxf(unsortable_bits(thr), 0.f);
        for (int j = tid; j < ce; j += NTHREADS) {
            const unsigned short me = eq_idx[j];
            int r = 0;
            for (int i = 0; i < ce; ++i) r += (eq_idx[i] < me) ? 1 : 0;
            if (r < need_eq) orow[me] = thr_relu;
        }
    }
}

extern "C" void kernel_launch(void* const* d_in, const int* in_sizes, int n_in,
                              void* d_out, int out_size) {
    const float* x = (const float*)d_in[0];
    float* out = (float*)d_out;
    const int rows = in_sizes[0] / COLS;
    topk_scatter_kernel<<<rows, NTHREADS>>>(x, out);
}

// round 17
// speedup vs baseline: 1.5730x; 1.5730x over previous
#include <cuda_runtime.h>
#include <cstdint>

#define COLS      32768
#define K_TOP     64
#define NTHREADS  512
#define CAP       4096
#define EQCAP     256
#define PIVOT     2.0f      // well below the expected 64th-largest (~2.88σ); slow path covers the rest

__device__ __forceinline__ unsigned sortable_bits(float f) {
    unsigned u = __float_as_uint(f);
    return (u & 0x80000000u) ? ~u : (u | 0x80000000u);
}
__device__ __forceinline__ float unsortable_bits(unsigned s) {
    unsigned u = (s & 0x80000000u) ? (s & 0x7fffffffu) : ~s;
    return __uint_as_float(u);
}

// 256-bit streaming load/store (sm_100+). 32B alignment guaranteed by indexing.
__device__ __forceinline__ void ldg256_cs(const float* p, float* v) {
    asm volatile("ld.global.cs.v8.f32 {%0,%1,%2,%3,%4,%5,%6,%7}, [%8];"
                 : "=f"(v[0]), "=f"(v[1]), "=f"(v[2]), "=f"(v[3]),
                   "=f"(v[4]), "=f"(v[5]), "=f"(v[6]), "=f"(v[7])
                 : "l"(p));
}
__device__ __forceinline__ void stg256_zero_cs(float* p) {
    asm volatile("st.global.cs.v8.f32 [%0], {%1,%2,%3,%4,%5,%6,%7,%8};"
                 :: "l"(p),
                    "f"(0.f), "f"(0.f), "f"(0.f), "f"(0.f),
                    "f"(0.f), "f"(0.f), "f"(0.f), "f"(0.f)
                 : "memory");
}

__global__ __launch_bounds__(NTHREADS, 4)
void topk_scatter_kernel(const float* __restrict__ x, float* __restrict__ out) {
    __shared__ unsigned       cand_bits[CAP];
    __shared__ unsigned short cand_idx[CAP];
    __shared__ unsigned short eq_idx[EQCAP];
    __shared__ int            hist[256];
    __shared__ int            ncand_s;
    __shared__ unsigned       cur_s;
    __shared__ int            k_s;
    __shared__ int            cnt_s;
    __shared__ int            eq_cnt;

    const int row = blockIdx.x;
    const int tid = threadIdx.x;
    const int lane = tid & 31;

    const float* __restrict__ xrow = x + (size_t)row * COLS;
    float* __restrict__       orow = out + (size_t)row * COLS;

    if (tid == 0) { ncand_s = 0; eq_cnt = 0; }
    __syncthreads();

    // ---------------- Phase A: fused pass — 256-bit stream-read + 256-bit zero-write,
    // ---------------- interleaved ld/st; candidate check per 32B chunk; rare smem compaction.
    // Row = 4096 float8-chunks; 512 threads -> 8 chunks/thread; 2 chunks (64B) in flight/step.
    {
        const float* xp = xrow + (size_t)tid * 8;
        float*       op = orow + (size_t)tid * 8;
        constexpr size_t STRIDE = (size_t)NTHREADS * 8;          // elements per chunk-wave
        int jbase = tid * 8;                                     // element index of chunk 0

        constexpr int CHUNKS = COLS / 8 / NTHREADS;              // 8
        #pragma unroll
        for (int i = 0; i < CHUNKS; i += 2) {
            float a[8], b[8];
            ldg256_cs(xp, a);
            stg256_zero_cs(op);
            ldg256_cs(xp + STRIDE, b);
            stg256_zero_cs(op + STRIDE);

            // one 8-wide check per 32B chunk (taken ~16.8%)
            #pragma unroll
            for (int h = 0; h < 2; ++h) {
                const float* w = h ? b : a;
                const int j8 = jbase + (h ? (int)STRIDE : 0);
                float m01 = fmaxf(w[0], w[1]), m23 = fmaxf(w[2], w[3]);
                float m45 = fmaxf(w[4], w[5]), m67 = fmaxf(w[6], w[7]);
                if (fmaxf(fmaxf(m01, m23), fmaxf(m45, m67)) >= PIVOT) {
                    #pragma unroll
                    for (int c = 0; c < 8; ++c) {
                        const float val = w[c];
                        if (val >= PIVOT) {
                            int pos = atomicAdd(&ncand_s, 1);
                            if (pos < CAP) {
                                cand_bits[pos] = __float_as_uint(val);  // positive -> bit order = value order
                                cand_idx[pos]  = (unsigned short)(j8 + c);
                            }
                        }
                    }
                }
            }
            xp += 2 * STRIDE;
            op += 2 * STRIDE;
            jbase += 2 * (int)STRIDE;
        }
    }
    __syncthreads();
    const int ncand = ncand_s;

    if (ncand >= K_TOP && ncand <= CAP) {
        // ---------------- Phase B: 4x8-bit radix select, K-th largest among candidates ----------------
        if (tid == 0) { cur_s = 0u; k_s = K_TOP; }
        #pragma unroll
        for (int pass = 0; pass < 4; ++pass) {
            const int shift = 24 - 8 * pass;
            if (tid < 256) hist[tid] = 0;
            __syncthreads();

            const unsigned cur = cur_s;
            const int k = k_s;
            for (int j = tid; j < ncand; j += NTHREADS) {
                unsigned u = cand_bits[j];
                bool match = (pass == 0) || ((u >> (shift + 8)) == cur);
                if (match) atomicAdd(&hist[(u >> shift) & 255u], 1);
            }
            __syncthreads();

            if (tid < 32) {
                // lane l owns digits [255-8l .. 248-8l], top-down
                int h[8]; int s = 0;
                #pragma unroll
                for (int q = 0; q < 8; ++q) { h[q] = hist[255 - 8 * lane - q]; s += h[q]; }
                int pre = s;
                #pragma unroll
                for (int d = 1; d < 32; d <<= 1) {
                    int t2 = __shfl_up_sync(0xffffffffu, pre, d);
                    if (lane >= d) pre += t2;
                }
                pre -= s;  // exclusive prefix (count of strictly larger digits)
                bool hit = (pre < k) && (pre + s >= k);
                unsigned hm = __ballot_sync(0xffffffffu, hit);
                int hl = __ffs(hm) - 1;
                if (lane == hl) {
                    int acc = pre;
                    #pragma unroll
                    for (int q = 0; q < 8; ++q) {
                        int d = 255 - 8 * lane - q;
                        if (acc + h[q] >= k) { cur_s = (cur << 8) | (unsigned)d; k_s = k - acc; break; }
                        acc += h[q];
                    }
                }
            }
            __syncthreads();
        }
        const unsigned thr_bits = cur_s;              // exact K-th largest (positive float bits)
        const int      need_eq  = k_s;                // # of tied-at-threshold elements to KEEP
        const float    thr_f    = __uint_as_float(thr_bits);

        // ---------------- Phase C: scatter strictly-greater winners; collect boundary ties ----------------
        for (int j = tid; j < ncand; j += NTHREADS) {
            unsigned u = cand_bits[j];
            if (u > thr_bits) {
                orow[cand_idx[j]] = fmaxf(__uint_as_float(u), 0.f);
            } else if (u == thr_bits) {
                int p = atomicAdd(&eq_cnt, 1);
                if (p < EQCAP) eq_idx[p] = cand_idx[j];
            }
        }
        __syncthreads();

        // Tie-break like XLA top_k: among equal values, lowest indices win.
        const int ce = (eq_cnt < EQCAP) ? eq_cnt : EQCAP;
        const float thr_relu = fmaxf(thr_f, 0.f);
        for (int j = tid; j < ce; j += NTHREADS) {
            const unsigned short me = eq_idx[j];
            int r = 0;
            for (int i = 0; i < ce; ++i) r += (eq_idx[i] < me) ? 1 : 0;
            if (r < need_eq) orow[me] = thr_relu;
        }
    } else {
        // ---------------- Slow path (general, exact; never triggers for this input) ----------------
        // Output row already zeroed by Phase A.

        // 32-step bit-descend: largest thr with count(bits >= thr) >= K  ==  bits of K-th largest
        unsigned thr = 0u;
        for (int b = 31; b >= 0; --b) {
            const unsigned T = thr | (1u << b);
            if (tid == 0) cnt_s = 0;
            __syncthreads();
            int c = 0;
            for (int j = tid; j < COLS; j += NTHREADS)
                c += (sortable_bits(xrow[j]) >= T) ? 1 : 0;
            #pragma unroll
            for (int d = 16; d; d >>= 1) c += __shfl_down_sync(0xffffffffu, c, d);
            if (lane == 0) atomicAdd(&cnt_s, c);
            __syncthreads();
            if (cnt_s >= K_TOP) thr = T;
            __syncthreads();               // protect cnt_s read vs next-iter reset
        }

        // count strictly greater -> need_eq
        if (tid == 0) cnt_s = 0;
        __syncthreads();
        {
            int c = 0;
            for (int j = tid; j < COLS; j += NTHREADS)
                c += (sortable_bits(xrow[j]) > thr) ? 1 : 0;
            #pragma unroll
            for (int d = 16; d; d >>= 1) c += __shfl_down_sync(0xffffffffu, c, d);
            if (lane == 0) atomicAdd(&cnt_s, c);
        }
        __syncthreads();
        const int need_eq = K_TOP - cnt_s;
        __syncthreads();

        // scatter strictly-greater; collect ties
        for (int j = tid; j < COLS; j += NTHREADS) {
            float v = xrow[j];
            unsigned s = sortable_bits(v);
            if (s > thr) {
                orow[j] = fmaxf(v, 0.f);
            } else if (s == thr) {
                int p = atomicAdd(&eq_cnt, 1);
                if (p < EQCAP) eq_idx[p] = (unsigned short)j;
            }
        }
        __syncthreads();
        const int ce = (eq_cnt < EQCAP) ? eq_cnt : EQCAP;
        const float thr_relu = fmaxf(unsortable_bits(thr), 0.f);
        for (int j = tid; j < ce; j += NTHREADS) {
            const unsigned short me = eq_idx[j];
            int r = 0;
            for (int i = 0; i < ce; ++i) r += (eq_idx[i] < me) ? 1 : 0;
            if (r < need_eq) orow[me] = thr_relu;
        }
    }
}

extern "C" void kernel_launch(void* const* d_in, const int* in_sizes, int n_in,
                              void* d_out, int out_size) {
    const float* x = (const float*)d_in[0];
    float* out = (float*)d_out;
    const int rows = in_sizes[0] / COLS;
    topk_scatter_kernel<<<rows, NTHREADS>>>(x, out);
}